// round 5
// baseline (speedup 1.0000x reference)
#include <cuda_runtime.h>
#include <cuda_bf16.h>
#include <math.h>
#include <stdint.h>

// Problem constants
#define BATCH 4
#define TLEN 1024
#define EMB 512
#define VOC 50257
#define MALL (BATCH * TLEN)          // 4096 rows

// MMA tiling (shared by all tensor GEMMs)
#define BM 128
#define BN 128
#define BKC 32                        // k per chunk (bf16)
#define ROWB 80                       // SMEM row stride bytes (conflict-free)
#define TILE_SM (128 * ROWB)          // 10240 B per tile
#define STAGE_SM (4 * TILE_SM)        // AH, AL, BH, BL = 40960 B
#define SMEM_2ST (2 * STAGE_SM)       // 81920
#define SMEM_3ST (3 * STAGE_SM)       // 122880

// lm_head specifics
#define NCHUNK_LM (EMB / BKC)         // 16
#define NTILES_M (MALL / BM)          // 32
#define NTILES_N 393                  // ceil(50257/128)
#define N_PAD (NTILES_N * BN)         // 50304

// split-bf16 operand buffers
static __device__ __nv_bfloat16 g_Xh[MALL * EMB];
static __device__ __nv_bfloat16 g_Xl[MALL * EMB];
static __device__ __nv_bfloat16 g_Wth[3 * EMB * EMB];   // [Wk^T, Wq^T, Wv^T] hi
static __device__ __nv_bfloat16 g_Wtl[3 * EMB * EMB];
static __device__ __nv_bfloat16 g_KQVh[3 * MALL * EMB]; // [K, Q, V] hi
static __device__ __nv_bfloat16 g_KQVl[3 * MALL * EMB];
static __device__ __nv_bfloat16 g_Vth[MALL * EMB];      // V^T per batch [512,1024]
static __device__ __nv_bfloat16 g_Vtl[MALL * EMB];
static __device__ float         g_WEI[BATCH * TLEN * TLEN];
static __device__ __nv_bfloat16 g_ATTh[BATCH * TLEN * TLEN];
static __device__ __nv_bfloat16 g_ATTl[BATCH * TLEN * TLEN];
static __device__ __nv_bfloat16 g_Oh[MALL * EMB];
static __device__ __nv_bfloat16 g_Ol[MALL * EMB];
static __device__ __nv_bfloat16 g_Bth[(size_t)N_PAD * EMB];  // W_lm^T hi
static __device__ __nv_bfloat16 g_Btl[(size_t)N_PAD * EMB];
static __device__ float g_cmax[BATCH * TLEN];
static __device__ float g_csum[BATCH * TLEN];
static __device__ float g_rowloss[MALL];

// ============================================================================
// PTX helpers (arch-portable: sm_80-era instructions only)
// ============================================================================
__device__ __forceinline__ uint32_t smem_u32(const void* p) {
    uint32_t a;
    asm("{ .reg .u64 t; cvta.to.shared.u64 t, %1; cvt.u32.u64 %0, t; }"
        : "=r"(a) : "l"(p));
    return a;
}
__device__ __forceinline__ void cp_async16(uint32_t dst, const void* src) {
    asm volatile("cp.async.cg.shared.global [%0], [%1], 16;"
                 :: "r"(dst), "l"(src) : "memory");
}
__device__ __forceinline__ void cp_commit() {
    asm volatile("cp.async.commit_group;" ::: "memory");
}
template <int N>
__device__ __forceinline__ void cp_wait() {
    asm volatile("cp.async.wait_group %0;" :: "n"(N) : "memory");
}
__device__ __forceinline__ void ldm_x4(uint32_t* r, uint32_t addr) {
    asm volatile("ldmatrix.sync.aligned.m8n8.x4.shared.b16 {%0,%1,%2,%3}, [%4];"
                 : "=r"(r[0]), "=r"(r[1]), "=r"(r[2]), "=r"(r[3]) : "r"(addr));
}
__device__ __forceinline__ void mma16816(float* c, const uint32_t* a,
                                         uint32_t b0, uint32_t b1) {
    asm volatile(
        "mma.sync.aligned.m16n8k16.row.col.f32.bf16.bf16.f32 "
        "{%0,%1,%2,%3}, {%4,%5,%6,%7}, {%8,%9}, {%0,%1,%2,%3};"
        : "+f"(c[0]), "+f"(c[1]), "+f"(c[2]), "+f"(c[3])
        : "r"(a[0]), "r"(a[1]), "r"(a[2]), "r"(a[3]), "r"(b0), "r"(b1));
}
__device__ __forceinline__ void split_store2(__nv_bfloat16* ph, __nv_bfloat16* pl,
                                             float v0, float v1) {
    __nv_bfloat162 h, l;
    h.x = __float2bfloat16(v0);
    h.y = __float2bfloat16(v1);
    l.x = __float2bfloat16(v0 - __bfloat162float(h.x));
    l.y = __float2bfloat16(v1 - __bfloat162float(h.y));
    *(__nv_bfloat162*)ph = h;
    *(__nv_bfloat162*)pl = l;
}

// ============================================================================
// Embedding: x = tok_emb[idx] + pos_emb, written pre-split (bf16 hi/lo)
// ============================================================================
__global__ void embed_kernel(const int* __restrict__ idx,
                             const float* __restrict__ tok,
                             const float* __restrict__ pos,
                             __nv_bfloat16* __restrict__ xh,
                             __nv_bfloat16* __restrict__ xl) {
    int n = blockIdx.x;
    int t = n & (TLEN - 1);
    int e4 = threadIdx.x;
    int token = __ldg(&idx[n]);
    float4 a = *(const float4*)&tok[(size_t)token * EMB + e4 * 4];
    float4 p = *(const float4*)&pos[(size_t)t * EMB + e4 * 4];
    a.x += p.x; a.y += p.y; a.z += p.z; a.w += p.w;
    size_t o = (size_t)n * EMB + e4 * 4;
    split_store2(xh + o, xl + o, a.x, a.y);
    split_store2(xh + o + 2, xl + o + 2, a.z, a.w);
}

// ============================================================================
// fp32 [K,N] -> transposed split bf16 [N_out(padded), K], rows >= N zeroed
// ============================================================================
__global__ void transpose_split_kernel(const float* __restrict__ W,
                                       __nv_bfloat16* __restrict__ bh,
                                       __nv_bfloat16* __restrict__ bl,
                                       int N, int K_) {
    __shared__ float t[32][33];
    int n0 = blockIdx.x * 32;
    int k0 = blockIdx.y * 32;
    for (int r = threadIdx.y; r < 32; r += 8) {
        int n = n0 + threadIdx.x;
        t[r][threadIdx.x] = (n < N) ? W[(size_t)(k0 + r) * N + n] : 0.f;
    }
    __syncthreads();
    for (int r = threadIdx.y; r < 32; r += 8) {
        float x = t[threadIdx.x][r];             // W[k0+tx][n0+r]
        __nv_bfloat16 h = __float2bfloat16(x);
        size_t o = (size_t)(n0 + r) * K_ + k0 + threadIdx.x;
        bh[o] = h;
        bl[o] = __float2bfloat16(x - __bfloat162float(h));
    }
}

// bf16 [rows, cols] -> [cols, rows] per batch z
__global__ void transpose_bf16_kernel(const __nv_bfloat16* __restrict__ src,
                                      __nv_bfloat16* __restrict__ dst,
                                      int rows, int cols) {
    __shared__ __nv_bfloat16 t[32][33];
    src += (size_t)blockIdx.z * rows * cols;
    dst += (size_t)blockIdx.z * rows * cols;
    int c0 = blockIdx.x * 32;
    int r0 = blockIdx.y * 32;
    for (int r = threadIdx.y; r < 32; r += 8)
        t[r][threadIdx.x] = src[(size_t)(r0 + r) * cols + c0 + threadIdx.x];
    __syncthreads();
    for (int r = threadIdx.y; r < 32; r += 8)
        dst[(size_t)(c0 + r) * rows + r0 + threadIdx.x] = t[threadIdx.x][r];
}

// ============================================================================
// Generic split-bf16 NT MMA GEMM: C = alpha * (Ah+Al) @ (Bh+Bl)^T
// A [M,K] row-major (lda), B [N,K] row-major (ldb), 3 MMA passes.
// SPLIT_OUT: write bf16 hi/lo pair; else fp32. Batched via blockIdx.z.
// All dims multiples of 128/32, 2-stage cp.async pipeline.
// ============================================================================
template <bool SPLIT_OUT>
__global__ __launch_bounds__(256, 1)
void mma_nt_kernel(const __nv_bfloat16* __restrict__ Ah,
                   const __nv_bfloat16* __restrict__ Al, int lda, long long sA,
                   const __nv_bfloat16* __restrict__ Bh,
                   const __nv_bfloat16* __restrict__ Bl, int ldb, long long sB,
                   int nchunk, float alpha,
                   float* __restrict__ Cf,
                   __nv_bfloat16* __restrict__ Ch,
                   __nv_bfloat16* __restrict__ Cl, int ldc, long long sC) {
    extern __shared__ char smem[];
    const uint32_t sbase = smem_u32(smem);
    const int tid = threadIdx.x;
    const int wid = tid >> 5;
    const int lane = tid & 31;
    const int m0 = blockIdx.y * BM;
    const int n0 = blockIdx.x * BN;
    const int z = blockIdx.z;
    const int wm = (wid >> 2) * 64;
    const int wn = (wid & 3) * 32;

    const __nv_bfloat16* srcs[4] = {
        Ah + (long long)z * sA + (size_t)m0 * lda,
        Al + (long long)z * sA + (size_t)m0 * lda,
        Bh + (long long)z * sB + (size_t)n0 * ldb,
        Bl + (long long)z * sB + (size_t)n0 * ldb };
    const int lds[4] = { lda, lda, ldb, ldb };

    float acc[4][4][4];
#pragma unroll
    for (int i = 0; i < 4; ++i)
#pragma unroll
        for (int j = 0; j < 4; ++j)
#pragma unroll
            for (int q = 0; q < 4; ++q) acc[i][j][q] = 0.f;

    auto issue = [&](int chunk, int stage) {
#pragma unroll
        for (int j = 0; j < 8; ++j) {
            int idx = tid + j * 256;
            int t = idx >> 9;
            int r = (idx >> 2) & 127;
            int c = idx & 3;
            const void* g = srcs[t] + (size_t)r * lds[t] + chunk * BKC + c * 8;
            uint32_t d = sbase + stage * STAGE_SM + t * TILE_SM + r * ROWB + c * 16;
            cp_async16(d, g);
        }
        cp_commit();
    };

    issue(0, 0);
    if (nchunk > 1) issue(1, 1);

    const int lrow = lane & 15;
    const int lcolhalf = (lane >> 4) * 16;

    for (int c = 0; c < nchunk; ++c) {
        if (c + 2 < nchunk) cp_wait<1>(); else cp_wait<0>();
        __syncthreads();

        uint32_t stg = sbase + (c & 1) * STAGE_SM;
#pragma unroll
        for (int ks = 0; ks < 2; ++ks) {
            uint32_t kb = ks * 32 + lcolhalf;
            uint32_t aH[4][4], aL[4][4], bH[2][4], bL[2][4];
#pragma unroll
            for (int mi = 0; mi < 4; ++mi) {
                uint32_t ro = (wm + mi * 16 + lrow) * ROWB + kb;
                ldm_x4(aH[mi], stg + 0 * TILE_SM + ro);
                ldm_x4(aL[mi], stg + 1 * TILE_SM + ro);
            }
#pragma unroll
            for (int g = 0; g < 2; ++g) {
                uint32_t ro = (wn + g * 16 + lrow) * ROWB + kb;
                ldm_x4(bH[g], stg + 2 * TILE_SM + ro);
                ldm_x4(bL[g], stg + 3 * TILE_SM + ro);
            }
#pragma unroll
            for (int mi = 0; mi < 4; ++mi)
#pragma unroll
                for (int nj = 0; nj < 4; ++nj) {
                    int g = nj >> 1, p = nj & 1;
                    mma16816(acc[mi][nj], aH[mi], bH[g][p], bH[g][p + 2]);
                    mma16816(acc[mi][nj], aH[mi], bL[g][p], bL[g][p + 2]);
                    mma16816(acc[mi][nj], aL[mi], bH[g][p], bH[g][p + 2]);
                }
        }
        __syncthreads();
        if (c + 2 < nchunk) issue(c + 2, c & 1);
    }

#pragma unroll
    for (int mi = 0; mi < 4; ++mi) {
#pragma unroll
        for (int nj = 0; nj < 4; ++nj) {
            int mrow = m0 + wm + mi * 16 + (lane >> 2);
            int ncol = n0 + wn + nj * 8 + (lane & 3) * 2;
            size_t o0 = (size_t)((long long)z * sC) + (size_t)mrow * ldc + ncol;
            size_t o1 = o0 + (size_t)8 * ldc;
            if (SPLIT_OUT) {
                split_store2(Ch + o0, Cl + o0,
                             alpha * acc[mi][nj][0], alpha * acc[mi][nj][1]);
                split_store2(Ch + o1, Cl + o1,
                             alpha * acc[mi][nj][2], alpha * acc[mi][nj][3]);
            } else {
                float2 r0 = make_float2(alpha * acc[mi][nj][0], alpha * acc[mi][nj][1]);
                float2 r1 = make_float2(alpha * acc[mi][nj][2], alpha * acc[mi][nj][3]);
                *(float2*)(Cf + o0) = r0;
                *(float2*)(Cf + o1) = r1;
            }
        }
    }
}

// ============================================================================
// Softmax over the QUERY axis (reference axis=1), causal-masked
// ============================================================================
__global__ void colstats_kernel(const float* __restrict__ wei,
                                float* __restrict__ cmax,
                                float* __restrict__ csum) {
    int b = blockIdx.y;
    int s = blockIdx.x * 32 + threadIdx.x;
    int ty = threadIdx.y;
    const float* w = wei + (size_t)b * TLEN * TLEN;
    float m = -INFINITY, l = 0.f;
    for (int t = ty; t < TLEN; t += 8) {
        if (t >= s) {
            float x = w[(size_t)t * TLEN + s];
            float nm = fmaxf(m, x);
            l = l * __expf(m - nm) + __expf(x - nm);
            m = nm;
        }
    }
    __shared__ float sm[8][33];
    __shared__ float sl[8][33];
    sm[ty][threadIdx.x] = m;
    sl[ty][threadIdx.x] = l;
    __syncthreads();
    if (ty == 0) {
        for (int j = 1; j < 8; ++j) {
            float m2 = sm[j][threadIdx.x], l2 = sl[j][threadIdx.x];
            if (l2 > 0.f) {
                float nm = fmaxf(m, m2);
                l = l * __expf(m - nm) + l2 * __expf(m2 - nm);
                m = nm;
            }
        }
        cmax[b * TLEN + s] = m;
        csum[b * TLEN + s] = l;
    }
}

// att = masked exp(wei - cmax)/csum, written pre-split (bf16 hi/lo)
__global__ void att_kernel(const float* __restrict__ wei,
                           const float* __restrict__ cmax,
                           const float* __restrict__ csum,
                           __nv_bfloat16* __restrict__ ah,
                           __nv_bfloat16* __restrict__ al) {
    size_t i = ((size_t)blockIdx.x * blockDim.x + threadIdx.x) * 2;
    int b = (int)(i >> 20);
    int r = (int)(i & (TLEN * TLEN - 1));
    int t = r >> 10;
    int s = r & (TLEN - 1);
    float v0 = 0.f, v1 = 0.f;
    if (t >= s)
        v0 = __expf(wei[i] - cmax[b * TLEN + s]) / csum[b * TLEN + s];
    if (t >= s + 1)
        v1 = __expf(wei[i + 1] - cmax[b * TLEN + s + 1]) / csum[b * TLEN + s + 1];
    split_store2(ah + i, al + i, v0, v1);
}

// ============================================================================
// lm_head MMA GEMM (3-stage pipeline): out = (Oh+Ol)(Bh+Bl)^T + bias
// ============================================================================
__global__ __launch_bounds__(256, 1)
void lmhead_mma_kernel(const __nv_bfloat16* __restrict__ Ah,
                       const __nv_bfloat16* __restrict__ Al,
                       const __nv_bfloat16* __restrict__ Bh,
                       const __nv_bfloat16* __restrict__ Bl,
                       const float* __restrict__ bias,
                       float* __restrict__ out) {
    extern __shared__ char smem[];
    const uint32_t sbase = smem_u32(smem);
    const int tid = threadIdx.x;
    const int wid = tid >> 5;
    const int lane = tid & 31;
    const int m0 = blockIdx.x * BM;
    const int n0 = blockIdx.y * BN;
    const int wm = (wid >> 2) * 64;
    const int wn = (wid & 3) * 32;

    const __nv_bfloat16* srcs[4] = {
        Ah + (size_t)m0 * EMB, Al + (size_t)m0 * EMB,
        Bh + (size_t)n0 * EMB, Bl + (size_t)n0 * EMB };

    float acc[4][4][4];
#pragma unroll
    for (int i = 0; i < 4; ++i)
#pragma unroll
        for (int j = 0; j < 4; ++j)
#pragma unroll
            for (int q = 0; q < 4; ++q) acc[i][j][q] = 0.f;

    auto issue = [&](int chunk, int stage) {
#pragma unroll
        for (int j = 0; j < 8; ++j) {
            int idx = tid + j * 256;
            int t = idx >> 9;
            int r = (idx >> 2) & 127;
            int c = idx & 3;
            const void* g = srcs[t] + (size_t)r * EMB + chunk * BKC + c * 8;
            uint32_t d = sbase + stage * STAGE_SM + t * TILE_SM + r * ROWB + c * 16;
            cp_async16(d, g);
        }
        cp_commit();
    };

    issue(0, 0);
    issue(1, 1);
    issue(2, 2);

    const int lrow = lane & 15;
    const int lcolhalf = (lane >> 4) * 16;

    for (int c = 0; c < NCHUNK_LM; ++c) {
        if (c <= NCHUNK_LM - 3) cp_wait<2>();
        else if (c == NCHUNK_LM - 2) cp_wait<1>();
        else cp_wait<0>();
        __syncthreads();

        uint32_t stg = sbase + (c % 3) * STAGE_SM;
#pragma unroll
        for (int ks = 0; ks < 2; ++ks) {
            uint32_t kb = ks * 32 + lcolhalf;
            uint32_t aH[4][4], aL[4][4], bH[2][4], bL[2][4];
#pragma unroll
            for (int mi = 0; mi < 4; ++mi) {
                uint32_t ro = (wm + mi * 16 + lrow) * ROWB + kb;
                ldm_x4(aH[mi], stg + 0 * TILE_SM + ro);
                ldm_x4(aL[mi], stg + 1 * TILE_SM + ro);
            }
#pragma unroll
            for (int g = 0; g < 2; ++g) {
                uint32_t ro = (wn + g * 16 + lrow) * ROWB + kb;
                ldm_x4(bH[g], stg + 2 * TILE_SM + ro);
                ldm_x4(bL[g], stg + 3 * TILE_SM + ro);
            }
#pragma unroll
            for (int mi = 0; mi < 4; ++mi)
#pragma unroll
                for (int nj = 0; nj < 4; ++nj) {
                    int g = nj >> 1, p = nj & 1;
                    mma16816(acc[mi][nj], aH[mi], bH[g][p], bH[g][p + 2]);
                    mma16816(acc[mi][nj], aH[mi], bL[g][p], bL[g][p + 2]);
                    mma16816(acc[mi][nj], aL[mi], bH[g][p], bH[g][p + 2]);
                }
        }
        __syncthreads();
        if (c + 3 < NCHUNK_LM) issue(c + 3, c % 3);
    }

#pragma unroll
    for (int mi = 0; mi < 4; ++mi) {
#pragma unroll
        for (int nj = 0; nj < 4; ++nj) {
            int mrow = m0 + wm + mi * 16 + (lane >> 2);
            int ncol = n0 + wn + nj * 8 + (lane & 3) * 2;
            float* p0 = out + (size_t)mrow * VOC + ncol;
            float* p1 = out + (size_t)(mrow + 8) * VOC + ncol;
            if (ncol < VOC) {
                float b0 = __ldg(&bias[ncol]);
                p0[0] = acc[mi][nj][0] + b0;
                p1[0] = acc[mi][nj][2] + b0;
            }
            if (ncol + 1 < VOC) {
                float b1 = __ldg(&bias[ncol + 1]);
                p0[1] = acc[mi][nj][1] + b1;
                p1[1] = acc[mi][nj][3] + b1;
            }
        }
    }
}

// ============================================================================
// Per-row NLL + mean
// ============================================================================
__global__ void rowloss_kernel(const float* __restrict__ logits,
                               const int* __restrict__ target,
                               float* __restrict__ rowloss) {
    int row = blockIdx.x;
    const float* p = logits + (size_t)row * VOC;
    float m = -INFINITY, l = 0.f;
    for (int j = threadIdx.x; j < VOC; j += blockDim.x) {
        float x = p[j];
        float nm = fmaxf(m, x);
        l = l * __expf(m - nm) + __expf(x - nm);
        m = nm;
    }
#pragma unroll
    for (int off = 16; off; off >>= 1) {
        float m2 = __shfl_xor_sync(0xFFFFFFFFu, m, off);
        float l2 = __shfl_xor_sync(0xFFFFFFFFu, l, off);
        float nm = fmaxf(m, m2);
        l = l * __expf(m - nm) + l2 * __expf(m2 - nm);
        m = nm;
    }
    __shared__ float sm[8], sl[8];
    int w = threadIdx.x >> 5;
    if ((threadIdx.x & 31) == 0) { sm[w] = m; sl[w] = l; }
    __syncthreads();
    if (threadIdx.x == 0) {
        m = sm[0]; l = sl[0];
        for (int j = 1; j < 8; ++j) {
            float m2 = sm[j], l2 = sl[j];
            float nm = fmaxf(m, m2);
            l = l * __expf(m - nm) + l2 * __expf(m2 - nm);
            m = nm;
        }
        float lse = m + logf(l);
        rowloss[row] = lse - p[target[row]];
    }
}

__global__ void loss_reduce_kernel(const float* __restrict__ rowloss,
                                   float* __restrict__ out) {
    __shared__ float s[256];
    float acc = 0.f;
    for (int j = threadIdx.x; j < MALL; j += 256) acc += rowloss[j];
    s[threadIdx.x] = acc;
    __syncthreads();
    for (int o = 128; o; o >>= 1) {
        if (threadIdx.x < o) s[threadIdx.x] += s[threadIdx.x + o];
        __syncthreads();
    }
    if (threadIdx.x == 0) *out = s[0] / (float)MALL;
}

// ============================================================================
extern "C" void kernel_launch(void* const* d_in, const int* in_sizes, int n_in,
                              void* d_out, int out_size) {
    const int*   idx    = (const int*)d_in[0];
    const int*   target = (const int*)d_in[1];
    const float* tok    = (const float*)d_in[2];
    const float* pos    = (const float*)d_in[3];
    const float* Wk     = (const float*)d_in[4];
    const float* Wq     = (const float*)d_in[5];
    const float* Wv     = (const float*)d_in[6];
    const float* Wlm    = (const float*)d_in[7];
    const float* blm    = (const float*)d_in[8];
    float* out = (float*)d_out;

    __nv_bfloat16 *Xh, *Xl, *Wth, *Wtl, *KQVh, *KQVl, *Vth, *Vtl;
    __nv_bfloat16 *ATTh, *ATTl, *Oh, *Ol, *Bth, *Btl;
    float *WEI, *cmax, *csum, *rl;
    cudaGetSymbolAddress((void**)&Xh,   g_Xh);
    cudaGetSymbolAddress((void**)&Xl,   g_Xl);
    cudaGetSymbolAddress((void**)&Wth,  g_Wth);
    cudaGetSymbolAddress((void**)&Wtl,  g_Wtl);
    cudaGetSymbolAddress((void**)&KQVh, g_KQVh);
    cudaGetSymbolAddress((void**)&KQVl, g_KQVl);
    cudaGetSymbolAddress((void**)&Vth,  g_Vth);
    cudaGetSymbolAddress((void**)&Vtl,  g_Vtl);
    cudaGetSymbolAddress((void**)&WEI,  g_WEI);
    cudaGetSymbolAddress((void**)&ATTh, g_ATTh);
    cudaGetSymbolAddress((void**)&ATTl, g_ATTl);
    cudaGetSymbolAddress((void**)&Oh,   g_Oh);
    cudaGetSymbolAddress((void**)&Ol,   g_Ol);
    cudaGetSymbolAddress((void**)&Bth,  g_Bth);
    cudaGetSymbolAddress((void**)&Btl,  g_Btl);
    cudaGetSymbolAddress((void**)&cmax, g_cmax);
    cudaGetSymbolAddress((void**)&csum, g_csum);
    cudaGetSymbolAddress((void**)&rl,   g_rowloss);

    cudaFuncSetAttribute(lmhead_mma_kernel,
                         cudaFuncAttributeMaxDynamicSharedMemorySize, SMEM_3ST);
    cudaFuncSetAttribute(mma_nt_kernel<true>,
                         cudaFuncAttributeMaxDynamicSharedMemorySize, SMEM_2ST);
    cudaFuncSetAttribute(mma_nt_kernel<false>,
                         cudaFuncAttributeMaxDynamicSharedMemorySize, SMEM_2ST);

    const float scale = 0.044194173824159216f;  // 512^-0.5 (n_embed, not head)
    const long long sME = (long long)MALL * EMB;
    const long long sTE = (long long)TLEN * EMB;
    const long long sTT = (long long)TLEN * TLEN;
    const long long sEE = (long long)EMB * EMB;

    // 0) weight preprocessing: W_lm^T split (padded), W{k,q,v}^T split
    transpose_split_kernel<<<dim3(N_PAD / 32, EMB / 32), dim3(32, 8)>>>(
        Wlm, Bth, Btl, VOC, EMB);
    transpose_split_kernel<<<dim3(EMB / 32, EMB / 32), dim3(32, 8)>>>(
        Wk, Wth + 0 * sEE, Wtl + 0 * sEE, EMB, EMB);
    transpose_split_kernel<<<dim3(EMB / 32, EMB / 32), dim3(32, 8)>>>(
        Wq, Wth + 1 * sEE, Wtl + 1 * sEE, EMB, EMB);
    transpose_split_kernel<<<dim3(EMB / 32, EMB / 32), dim3(32, 8)>>>(
        Wv, Wth + 2 * sEE, Wtl + 2 * sEE, EMB, EMB);

    // 1) x = tok_emb[idx] + pos_emb (pre-split)
    embed_kernel<<<MALL, 128>>>(idx, tok, pos, Xh, Xl);

    // 2) [K,Q,V] = x @ W (one z-batched MMA launch, split outputs)
    mma_nt_kernel<true><<<dim3(EMB / BN, MALL / BM, 3), 256, SMEM_2ST>>>(
        Xh, Xl, EMB, 0, Wth, Wtl, EMB, sEE, EMB / BKC, 1.f,
        nullptr, KQVh, KQVl, EMB, sME);

    // 3) V^T per batch (for att @ v in NT form)
    transpose_bf16_kernel<<<dim3(EMB / 32, TLEN / 32, BATCH), dim3(32, 8)>>>(
        KQVh + 2 * sME, Vth, TLEN, EMB);
    transpose_bf16_kernel<<<dim3(EMB / 32, TLEN / 32, BATCH), dim3(32, 8)>>>(
        KQVl + 2 * sME, Vtl, TLEN, EMB);

    // 4) wei = scale * q @ k^T (fp32 out)
    mma_nt_kernel<false><<<dim3(TLEN / BN, TLEN / BM, BATCH), 256, SMEM_2ST>>>(
        KQVh + 1 * sME, KQVl + 1 * sME, EMB, sTE,
        KQVh + 0 * sME, KQVl + 0 * sME, EMB, sTE,
        EMB / BKC, scale, WEI, nullptr, nullptr, TLEN, sTT);

    // 5) softmax over the query axis; att written pre-split
    colstats_kernel<<<dim3(TLEN / 32, BATCH), dim3(32, 8)>>>(WEI, cmax, csum);
    att_kernel<<<(BATCH * TLEN * TLEN) / 512, 256>>>(WEI, cmax, csum, ATTh, ATTl);

    // 6) O = att @ v (split output, feeds lm_head directly)
    mma_nt_kernel<true><<<dim3(EMB / BN, TLEN / BM, BATCH), 256, SMEM_2ST>>>(
        ATTh, ATTl, TLEN, sTT, Vth, Vtl, TLEN, sTE,
        TLEN / BKC, 1.f, nullptr, Oh, Ol, EMB, sTE);

    // 7) logits = O @ W_lm + b_lm -> d_out
    lmhead_mma_kernel<<<dim3(NTILES_M, NTILES_N), 256, SMEM_3ST>>>(
        Oh, Ol, Bth, Btl, blm, out);

    // 8) loss
    rowloss_kernel<<<MALL, 256>>>(out, target, rl);
    loss_reduce_kernel<<<1, 256>>>(rl, out + (size_t)out_size - 1);
}